// round 10
// baseline (speedup 1.0000x reference)
#include <cuda_runtime.h>
#include <cuda_bf16.h>
#include <cstdint>

// ---------------------------------------------------------------------------
// Problem constants
// ---------------------------------------------------------------------------
#define MAX_NODES 100000
#define MAX_EDGES 1700000
#define DIM 128

// Scratch (no allocation allowed in kernel_launch)
__device__ int g_idx64;
__device__ __align__(16) __nv_bfloat16 g_whi[5][128 * 128];
__device__ __align__(16) __nv_bfloat16 g_wlo[5][128 * 128];
// CSR scratch
__device__ int g_cnt[MAX_NODES];
__device__ int g_off[MAX_NODES];
__device__ int g_cursor[MAX_NODES];
__device__ int g_eid[MAX_EDGES];
__device__ int g_bsum[256];
__device__ int g_bsumx[256];

// ---------------------------------------------------------------------------
// Helpers
// ---------------------------------------------------------------------------
__device__ __forceinline__ uint32_t smem_to_u32(const void* p) {
    uint32_t a;
    asm("{ .reg .u64 t; cvta.to.shared.u64 t, %1; cvt.u32.u64 %0, t; }"
        : "=r"(a) : "l"(p));
    return a;
}

__device__ __forceinline__ void ldsm4(uint32_t* r, uint32_t addr) {
    asm volatile("ldmatrix.sync.aligned.m8n8.x4.shared.b16 {%0,%1,%2,%3}, [%4];\n"
                 : "=r"(r[0]), "=r"(r[1]), "=r"(r[2]), "=r"(r[3]) : "r"(addr));
}

__device__ __forceinline__ void mma16816(float* c, const uint32_t* a,
                                         const uint32_t* b) {
    asm volatile(
        "mma.sync.aligned.m16n8k16.row.col.f32.bf16.bf16.f32 "
        "{%0,%1,%2,%3}, {%4,%5,%6,%7}, {%8,%9}, {%0,%1,%2,%3};\n"
        : "+f"(c[0]), "+f"(c[1]), "+f"(c[2]), "+f"(c[3])
        : "r"(a[0]), "r"(a[1]), "r"(a[2]), "r"(a[3]), "r"(b[0]), "r"(b[1]));
}

#define BAR_SYNC(id, cnt) \
    asm volatile("bar.sync %0, %1;" :: "r"(id), "r"(cnt) : "memory")
#define BAR_ARRIVE(id, cnt) \
    asm volatile("bar.arrive %0, %1;" :: "r"(id), "r"(cnt) : "memory")

__device__ __forceinline__ uint32_t pack_hilo(float v0, float v1, uint32_t& lo) {
    __nv_bfloat16 h0 = __float2bfloat16(v0);
    __nv_bfloat16 h1 = __float2bfloat16(v1);
    __nv_bfloat16 l0 = __float2bfloat16(v0 - __bfloat162float(h0));
    __nv_bfloat16 l1 = __float2bfloat16(v1 - __bfloat162float(h1));
    __nv_bfloat162 hp; hp.x = h0; hp.y = h1;
    __nv_bfloat162 lp; lp.x = l0; lp.y = l1;
    lo = *(uint32_t*)&lp;
    return *(uint32_t*)&hp;
}

__device__ __forceinline__ int edge_dst(const void* ei, int nEdges, int edge) {
    if (g_idx64) return (int)((const long long*)ei)[(size_t)nEdges + edge];
    return ((const int*)ei)[(size_t)nEdges + edge];
}

#define ROWB 272
#define TILE_BYTES_PAD (128 * ROWB)   // 34816

// ---------------------------------------------------------------------------
// Kernel 0: detect edge_index dtype
// ---------------------------------------------------------------------------
__global__ void detect_kernel(const unsigned int* __restrict__ ei32) {
    unsigned int acc = 0;
#pragma unroll
    for (int k = 0; k < 8; ++k) acc |= ei32[2 * k + 1];
    g_idx64 = (acc == 0u) ? 1 : 0;
}

// ---------------------------------------------------------------------------
// CSR build kernels
// ---------------------------------------------------------------------------
__global__ void zero_cnt_kernel(int nNodes) {
    int i = blockIdx.x * blockDim.x + threadIdx.x;
    if (i < nNodes) g_cnt[i] = 0;
}

__global__ void hist_kernel(const void* __restrict__ ei, int nEdges, int nNodes) {
    int i = blockIdx.x * blockDim.x + threadIdx.x;
    if (i >= nEdges) return;
    int dst = edge_dst(ei, nEdges, i);
    if ((unsigned)dst < (unsigned)nNodes) atomicAdd(&g_cnt[dst], 1);
}

__global__ void scan1_kernel(int nNodes) {
    __shared__ int wsum[32];
    int i = blockIdx.x * 1024 + threadIdx.x;
    int lane = threadIdx.x & 31, w = threadIdx.x >> 5;
    int v = (i < nNodes) ? g_cnt[i] : 0;
    int inc = v;
#pragma unroll
    for (int off = 1; off < 32; off <<= 1) {
        int t = __shfl_up_sync(0xffffffffu, inc, off);
        if (lane >= off) inc += t;
    }
    if (lane == 31) wsum[w] = inc;
    __syncthreads();
    if (w == 0) {
        int s = (lane < 32) ? wsum[lane] : 0;
#pragma unroll
        for (int off = 1; off < 32; off <<= 1) {
            int t = __shfl_up_sync(0xffffffffu, s, off);
            if (lane >= off) s += t;
        }
        wsum[lane] = s;
    }
    __syncthreads();
    int base = (w > 0) ? wsum[w - 1] : 0;
    int excl = base + inc - v;
    if (i < nNodes) g_off[i] = excl;
    if (threadIdx.x == 1023) g_bsum[blockIdx.x] = base + inc;
}

__global__ void scan2_kernel(int nblocks) {
    if (threadIdx.x == 0) {
        int s = 0;
        for (int b = 0; b < nblocks; ++b) { g_bsumx[b] = s; s += g_bsum[b]; }
    }
}

__global__ void scan3_kernel(int nNodes) {
    int i = blockIdx.x * 1024 + threadIdx.x;
    if (i < nNodes) {
        int o = g_off[i] + g_bsumx[blockIdx.x];
        g_off[i] = o;
        g_cursor[i] = o;
    }
}

__global__ void fill_kernel(const void* __restrict__ ei, int nEdges, int nNodes) {
    int i = blockIdx.x * blockDim.x + threadIdx.x;
    if (i >= nEdges) return;
    int dst = edge_dst(ei, nEdges, i);
    if ((unsigned)dst >= (unsigned)nNodes) return;
    int pos = atomicAdd(&g_cursor[dst], 1);
    g_eid[pos] = i;
}

// ---------------------------------------------------------------------------
// Weight prep. B[n][k] = W[k][n], bf16 hi/lo.
// ---------------------------------------------------------------------------
__global__ void prep_weights(const float* __restrict__ W0,
                             const float* __restrict__ Wh,
                             const float* __restrict__ Wo) {
    int l = blockIdx.x;  // 0..4
    const float* src;
    if (l == 0)      src = W0;
    else if (l == 1) src = W0 + 128 * 128;
    else if (l == 2) src = Wh;
    else if (l == 3) src = Wh + 128 * 128;
    else             src = Wo;
    __nv_bfloat16* dh = g_whi[l];
    __nv_bfloat16* dl = g_wlo[l];
    for (int i = threadIdx.x; i < 128 * 128; i += blockDim.x) {
        int n = i >> 7, k = i & 127;
        float w = src[k * 128 + n];
        __nv_bfloat16 hi = __float2bfloat16(w);
        dh[i] = hi;
        dl[i] = __float2bfloat16(w - __bfloat162float(hi));
    }
}

// ---------------------------------------------------------------------------
// Fused persistent MLP kernel: 512 threads.
//   warps 0-7  : consumer (mma.sync MLP, 5 phases, GN + residual)
//   warps 8-15 : producer (CSR gather of next tile's msg -> bf16 hi/lo smem)
// Named barriers: 1 = msg-full (512), 2 = msg-free (512), 3 = consumer (256).
// ---------------------------------------------------------------------------
__device__ __forceinline__ void stage_A(const float* __restrict__ src, int m0,
                                        int nNodes, unsigned char* Ahi,
                                        unsigned char* Alo, int tid) {
#pragma unroll
    for (int i = 0; i < 16; ++i) {
        int id = i * 256 + tid;        // 0..4095 float4s
        int row = id >> 5;
        int k0 = (id & 31) << 2;
        float4 v = make_float4(0.f, 0.f, 0.f, 0.f);
        int node = m0 + row;
        if (node < nNodes) v = *(const float4*)&src[(size_t)node * DIM + k0];
        uint32_t l01, l23;
        uint32_t h01 = pack_hilo(v.x, v.y, l01);
        uint32_t h23 = pack_hilo(v.z, v.w, l23);
        uint2 uh; uh.x = h01; uh.y = h23;
        uint2 ul; ul.x = l01; ul.y = l23;
        *(uint2*)(Ahi + row * ROWB + k0 * 2) = uh;
        *(uint2*)(Alo + row * ROWB + k0 * 2) = ul;
    }
}

__device__ __forceinline__ void stage_B(int l, unsigned char* Bhi,
                                        unsigned char* Blo, int tid) {
    const float4* sh = (const float4*)g_whi[l];
    const float4* sl = (const float4*)g_wlo[l];
#pragma unroll
    for (int i = 0; i < 8; ++i) {
        int id = i * 256 + tid;        // 0..2047 float4s (16 per row)
        int row = id >> 4;
        int c16 = id & 15;
        *(float4*)(Bhi + row * ROWB + c16 * 16) = sh[id];
        *(float4*)(Blo + row * ROWB + c16 * 16) = sl[id];
    }
}

__device__ __forceinline__ void clear_acc(float acc[2][8][4]) {
#pragma unroll
    for (int m = 0; m < 2; ++m)
#pragma unroll
        for (int n = 0; n < 8; ++n)
#pragma unroll
            for (int c = 0; c < 4; ++c) acc[m][n][c] = 0.f;
}

__device__ __forceinline__ void gemm_unit(float acc[2][8][4],
                                          uint32_t AHI, uint32_t ALO,
                                          uint32_t BHI, uint32_t BLO,
                                          uint32_t aoff, uint32_t boff) {
#pragma unroll
    for (int k0 = 0; k0 < 128; k0 += 16) {
        uint32_t ah[2][4], al[2][4];
        ldsm4(ah[0], AHI + aoff + k0 * 2);
        ldsm4(ah[1], AHI + aoff + 16 * ROWB + k0 * 2);
        ldsm4(al[0], ALO + aoff + k0 * 2);
        ldsm4(al[1], ALO + aoff + 16 * ROWB + k0 * 2);
#pragma unroll
        for (int g = 0; g < 4; ++g) {
            uint32_t bh[4], bl[4];
            ldsm4(bh, BHI + boff + g * 16 * ROWB + k0 * 2);
            ldsm4(bl, BLO + boff + g * 16 * ROWB + k0 * 2);
#pragma unroll
            for (int t = 0; t < 2; ++t) {
                int nt = g * 2 + t;
#pragma unroll
                for (int mt = 0; mt < 2; ++mt) {
                    mma16816(acc[mt][nt], ah[mt], bh + t * 2);
                    mma16816(acc[mt][nt], ah[mt], bl + t * 2);
                    mma16816(acc[mt][nt], al[mt], bh + t * 2);
                }
            }
        }
    }
}

__device__ __forceinline__ void epi_relu(float acc[2][8][4],
                                         const float* __restrict__ sbias,
                                         unsigned char* Ahi, unsigned char* Alo,
                                         int warp_m, int warp_n, int lane) {
    int rbase = warp_m * 32 + (lane >> 2);
    int cbase = warp_n * 64 + 2 * (lane & 3);
#pragma unroll
    for (int mt = 0; mt < 2; ++mt) {
#pragma unroll
        for (int nt = 0; nt < 8; ++nt) {
            int c = cbase + nt * 8;
            float bb0 = sbias[c], bb1 = sbias[c + 1];
            int r0 = rbase + mt * 16;
            float v0 = fmaxf(acc[mt][nt][0] + bb0, 0.f);
            float v1 = fmaxf(acc[mt][nt][1] + bb1, 0.f);
            float v2 = fmaxf(acc[mt][nt][2] + bb0, 0.f);
            float v3 = fmaxf(acc[mt][nt][3] + bb1, 0.f);
            uint32_t lo;
            uint32_t hi = pack_hilo(v0, v1, lo);
            *(uint32_t*)(Ahi + r0 * ROWB + c * 2) = hi;
            *(uint32_t*)(Alo + r0 * ROWB + c * 2) = lo;
            hi = pack_hilo(v2, v3, lo);
            *(uint32_t*)(Ahi + (r0 + 8) * ROWB + c * 2) = hi;
            *(uint32_t*)(Alo + (r0 + 8) * ROWB + c * 2) = lo;
        }
    }
}

// smem: header 5120 + A(hi/lo) + M(hi/lo) + B(hi/lo)
#define SMEM_AOFF 5120
#define SMEM_TOTAL_MLP (SMEM_AOFF + 6 * TILE_BYTES_PAD)   // 214016

__global__ __launch_bounds__(512, 1)
void mlp_fused_kernel(const float* __restrict__ x,
                      const float* __restrict__ e,
                      const float* __restrict__ b0v,
                      const float* __restrict__ bhv,
                      const float* __restrict__ bov,
                      const float* __restrict__ gnw,
                      const float* __restrict__ gnb,
                      float* __restrict__ out, int nNodes) {
    extern __shared__ unsigned char smem[];
    float* sb   = (float*)smem;            // [4][128] biases
    float* sgw  = (float*)(smem + 2048);
    float* sgb  = (float*)(smem + 2560);
    float* ps   = (float*)(smem + 3072);   // [2][128]
    float* pq   = (float*)(smem + 4096);   // [2][128]
    unsigned char* Ahi = smem + SMEM_AOFF;               // A: x, then h
    unsigned char* Alo = Ahi + TILE_BYTES_PAD;
    unsigned char* Mhi = Alo + TILE_BYTES_PAD;           // gathered msg
    unsigned char* Mlo = Mhi + TILE_BYTES_PAD;
    unsigned char* Bhi = Mlo + TILE_BYTES_PAD;
    unsigned char* Blo = Bhi + TILE_BYTES_PAD;

    const uint32_t sb32 = smem_to_u32(smem);
    const uint32_t AHI = sb32 + SMEM_AOFF;
    const uint32_t ALO = AHI + TILE_BYTES_PAD;
    const uint32_t MHI = ALO + TILE_BYTES_PAD;
    const uint32_t MLO = MHI + TILE_BYTES_PAD;
    const uint32_t BHI = MLO + TILE_BYTES_PAD;
    const uint32_t BLO = BHI + TILE_BYTES_PAD;

    const int tid = threadIdx.x;
    const int wid = tid >> 5, lane = tid & 31;
    const int nBlk = gridDim.x;
    const int nTiles = (nNodes + 127) >> 7;

    // number of tiles this block handles
    int ntb = 0;
    for (int t = blockIdx.x; t < nTiles; t += nBlk) ++ntb;

    if (wid >= 8) {
        // ================= PRODUCER (warps 8-15): gather next tile =========
        const int pwid = wid - 8;
        const int c = lane << 2;  // float chunk
        for (int k = 0; k < ntb; ++k) {
            if (k > 0) BAR_SYNC(2, 512);     // wait msg buffer free
            int m0 = (blockIdx.x + k * nBlk) << 7;
#pragma unroll 1
            for (int rr = 0; rr < 16; ++rr) {
                int r = pwid * 16 + rr;
                int node = m0 + r;
                float4 a4 = make_float4(0.f, 0.f, 0.f, 0.f);
                if (node < nNodes) {
                    int start = g_off[node];
                    int n = g_cnt[node];
                    int i = 0;
                    for (; i + 4 <= n; i += 4) {
                        int e0 = g_eid[start + i];
                        int e1 = g_eid[start + i + 1];
                        int e2 = g_eid[start + i + 2];
                        int e3 = g_eid[start + i + 3];
                        float4 v0 = __ldcs((const float4*)&e[(size_t)e0 * DIM + c]);
                        float4 v1 = __ldcs((const float4*)&e[(size_t)e1 * DIM + c]);
                        float4 v2 = __ldcs((const float4*)&e[(size_t)e2 * DIM + c]);
                        float4 v3 = __ldcs((const float4*)&e[(size_t)e3 * DIM + c]);
                        a4.x += v0.x + v1.x + v2.x + v3.x;
                        a4.y += v0.y + v1.y + v2.y + v3.y;
                        a4.z += v0.z + v1.z + v2.z + v3.z;
                        a4.w += v0.w + v1.w + v2.w + v3.w;
                    }
                    for (; i < n; ++i) {
                        int e0 = g_eid[start + i];
                        float4 v0 = __ldcs((const float4*)&e[(size_t)e0 * DIM + c]);
                        a4.x += v0.x; a4.y += v0.y; a4.z += v0.z; a4.w += v0.w;
                    }
                }
                uint32_t l01, l23;
                uint32_t h01 = pack_hilo(a4.x, a4.y, l01);
                uint32_t h23 = pack_hilo(a4.z, a4.w, l23);
                uint2 uh; uh.x = h01; uh.y = h23;
                uint2 ul; ul.x = l01; ul.y = l23;
                *(uint2*)(Mhi + r * ROWB + c * 2) = uh;
                *(uint2*)(Mlo + r * ROWB + c * 2) = ul;
            }
            __threadfence_block();
            BAR_ARRIVE(1, 512);              // signal msg full
        }
    } else {
        // ================= CONSUMER (warps 0-7): 5-phase MLP ===============
        const int warp_m = wid & 3, warp_n = wid >> 2;
        const uint32_t aoff =
            (uint32_t)(warp_m * 32 + (lane & 15)) * ROWB + (((lane >> 4) & 1) * 8) * 2;
        const uint32_t boff =
            (uint32_t)(warp_n * 64 + ((lane >> 4) & 1) * 8 + (lane & 7)) * ROWB +
            (((lane >> 3) & 1) * 8) * 2;

        if (tid < 128) {
            sb[tid]       = b0v[tid];
            sb[128 + tid] = bhv[tid];
            sb[256 + tid] = bhv[128 + tid];
            sb[384 + tid] = bov[tid];
            sgw[tid] = gnw[tid];
            sgb[tid] = gnb[tid];
        }
        BAR_SYNC(3, 256);

        float acc[2][8][4];
        for (int k = 0; k < ntb; ++k) {
            const int m0 = (blockIdx.x + k * nBlk) << 7;
            clear_acc(acc);

            // phase 0: A = x
            stage_A(x, m0, nNodes, Ahi, Alo, tid);
            stage_B(0, Bhi, Blo, tid);
            BAR_SYNC(3, 256);
            gemm_unit(acc, AHI, ALO, BHI, BLO, aoff, boff);
            BAR_SYNC(3, 256);

            // phase 1: A = gathered msg (producer)
            stage_B(1, Bhi, Blo, tid);
            BAR_SYNC(1, 512);                // wait msg full
            BAR_SYNC(3, 256);                // B1 visible
            gemm_unit(acc, MHI, MLO, BHI, BLO, aoff, boff);
            BAR_ARRIVE(2, 512);              // msg buffer free for next tile
            BAR_SYNC(3, 256);

            // phase 2: hidden 0
            epi_relu(acc, sb, Ahi, Alo, warp_m, warp_n, lane);
            clear_acc(acc);
            stage_B(2, Bhi, Blo, tid);
            BAR_SYNC(3, 256);
            gemm_unit(acc, AHI, ALO, BHI, BLO, aoff, boff);
            BAR_SYNC(3, 256);

            // phase 3: hidden 1
            epi_relu(acc, sb + 128, Ahi, Alo, warp_m, warp_n, lane);
            clear_acc(acc);
            stage_B(3, Bhi, Blo, tid);
            BAR_SYNC(3, 256);
            gemm_unit(acc, AHI, ALO, BHI, BLO, aoff, boff);
            BAR_SYNC(3, 256);

            // phase 4: output layer
            epi_relu(acc, sb + 256, Ahi, Alo, warp_m, warp_n, lane);
            clear_acc(acc);
            stage_B(4, Bhi, Blo, tid);
            BAR_SYNC(3, 256);
            gemm_unit(acc, AHI, ALO, BHI, BLO, aoff, boff);
            BAR_SYNC(3, 256);

            // GroupNorm + affine + residual
            const int rq = lane >> 2;
            const int cbase = warp_n * 64 + 2 * (lane & 3);
#pragma unroll
            for (int mt = 0; mt < 2; ++mt)
#pragma unroll
                for (int nt = 0; nt < 8; ++nt) {
                    int cc = cbase + nt * 8;
                    acc[mt][nt][0] += sb[384 + cc];
                    acc[mt][nt][1] += sb[384 + cc + 1];
                    acc[mt][nt][2] += sb[384 + cc];
                    acc[mt][nt][3] += sb[384 + cc + 1];
                }
            float s[4] = {0.f, 0.f, 0.f, 0.f}, q[4] = {0.f, 0.f, 0.f, 0.f};
#pragma unroll
            for (int mt = 0; mt < 2; ++mt)
#pragma unroll
                for (int nt = 0; nt < 8; ++nt) {
                    float a0 = acc[mt][nt][0], a1 = acc[mt][nt][1];
                    float a2 = acc[mt][nt][2], a3 = acc[mt][nt][3];
                    s[mt * 2]     += a0 + a1;
                    q[mt * 2]     += a0 * a0 + a1 * a1;
                    s[mt * 2 + 1] += a2 + a3;
                    q[mt * 2 + 1] += a2 * a2 + a3 * a3;
                }
#pragma unroll
            for (int off = 1; off <= 2; off <<= 1) {
#pragma unroll
                for (int i = 0; i < 4; ++i) {
                    s[i] += __shfl_xor_sync(0xffffffffu, s[i], off);
                    q[i] += __shfl_xor_sync(0xffffffffu, q[i], off);
                }
            }
            if ((lane & 3) == 0) {
                int r0 = warp_m * 32 + rq;
                ps[warp_n * 128 + r0]      = s[0];
                ps[warp_n * 128 + r0 + 8]  = s[1];
                ps[warp_n * 128 + r0 + 16] = s[2];
                ps[warp_n * 128 + r0 + 24] = s[3];
                pq[warp_n * 128 + r0]      = q[0];
                pq[warp_n * 128 + r0 + 8]  = q[1];
                pq[warp_n * 128 + r0 + 16] = q[2];
                pq[warp_n * 128 + r0 + 24] = q[3];
            }
            BAR_SYNC(3, 256);
#pragma unroll
            for (int mt = 0; mt < 2; ++mt) {
#pragma unroll
                for (int h = 0; h < 2; ++h) {
                    int r = warp_m * 32 + mt * 16 + h * 8 + rq;
                    float ts = ps[r] + ps[128 + r];
                    float tq = pq[r] + pq[128 + r];
                    float mean = ts * (1.f / 128.f);
                    float var = tq * (1.f / 128.f) - mean * mean;
                    float rstd = rsqrtf(var + 1e-5f);
                    int node = m0 + r;
                    if (node < nNodes) {
#pragma unroll
                        for (int nt = 0; nt < 8; ++nt) {
                            int cc = cbase + nt * 8;
                            float v0 = acc[mt][nt][h * 2 + 0];
                            float v1 = acc[mt][nt][h * 2 + 1];
                            float2 xv = *(const float2*)&x[(size_t)node * DIM + cc];
                            float2 o;
                            o.x = (v0 - mean) * rstd * sgw[cc]     + sgb[cc]     + xv.x;
                            o.y = (v1 - mean) * rstd * sgw[cc + 1] + sgb[cc + 1] + xv.y;
                            *(float2*)&out[(size_t)node * DIM + cc] = o;
                        }
                    }
                }
            }
            BAR_SYNC(3, 256);   // ps/pq + A region free before next tile
        }
    }
}

// ---------------------------------------------------------------------------
extern "C" void kernel_launch(void* const* d_in, const int* in_sizes, int n_in,
                              void* d_out, int out_size) {
    const float* x  = (const float*)d_in[0];
    const float* e  = (const float*)d_in[1];
    const void*  ei = d_in[2];
    const float* W0 = (const float*)d_in[3];
    const float* b0 = (const float*)d_in[4];
    const float* Wh = (const float*)d_in[5];
    const float* bh = (const float*)d_in[6];
    const float* Wo = (const float*)d_in[7];
    const float* bo = (const float*)d_in[8];
    const float* gnw = (const float*)d_in[9];
    const float* gnb = (const float*)d_in[10];
    float* out = (float*)d_out;

    int nNodes = in_sizes[0] / DIM;
    int nEdges = in_sizes[1] / DIM;
    if (nNodes > MAX_NODES) nNodes = MAX_NODES;
    if (nEdges > MAX_EDGES) nEdges = MAX_EDGES;

    cudaFuncSetAttribute(mlp_fused_kernel,
                         cudaFuncAttributeMaxDynamicSharedMemorySize,
                         SMEM_TOTAL_MLP);

    const int scanBlocks = (nNodes + 1023) / 1024;

    // 0) detect edge_index dtype
    detect_kernel<<<1, 1>>>((const unsigned int*)ei);

    // 1) weight prep
    prep_weights<<<5, 256>>>(W0, Wh, Wo);

    // 2) CSR build
    zero_cnt_kernel<<<(nNodes + 255) / 256, 256>>>(nNodes);
    hist_kernel<<<(nEdges + 255) / 256, 256>>>(ei, nEdges, nNodes);
    scan1_kernel<<<scanBlocks, 1024>>>(nNodes);
    scan2_kernel<<<1, 32>>>(scanBlocks);
    scan3_kernel<<<scanBlocks, 1024>>>(nNodes);
    fill_kernel<<<(nEdges + 255) / 256, 256>>>(ei, nEdges, nNodes);

    // 3) fused persistent gather + tensor-core MLP + GroupNorm + residual
    int nTiles = (nNodes + 127) / 128;
    int grid = nTiles < 148 ? nTiles : 148;
    mlp_fused_kernel<<<grid, 512, SMEM_TOTAL_MLP>>>(x, e, b0, bh, bo,
                                                    gnw, gnb, out, nNodes);
}

// round 11
// speedup vs baseline: 1.2133x; 1.2133x over previous
#include <cuda_runtime.h>
#include <cuda_bf16.h>
#include <cstdint>

// ---------------------------------------------------------------------------
// Problem constants
// ---------------------------------------------------------------------------
#define MAX_NODES 100000
#define MAX_EDGES 1700000
#define DIM 128

// Scratch (no allocation allowed in kernel_launch)
__device__ __align__(16) float g_msg[(size_t)MAX_NODES * DIM];
__device__ int g_idx64;
__device__ __align__(16) __nv_bfloat16 g_whi[5][128 * 128];
__device__ __align__(16) __nv_bfloat16 g_wlo[5][128 * 128];
// CSR scratch
__device__ int g_cnt[MAX_NODES];
__device__ int g_off[MAX_NODES];
__device__ int g_cursor[MAX_NODES];
__device__ int g_eid[MAX_EDGES];
__device__ int g_bsum[256];
__device__ int g_bsumx[256];

// ---------------------------------------------------------------------------
// Helpers
// ---------------------------------------------------------------------------
__device__ __forceinline__ uint32_t smem_to_u32(const void* p) {
    uint32_t a;
    asm("{ .reg .u64 t; cvta.to.shared.u64 t, %1; cvt.u32.u64 %0, t; }"
        : "=r"(a) : "l"(p));
    return a;
}

__device__ __forceinline__ void ldsm4(uint32_t* r, uint32_t addr) {
    asm volatile("ldmatrix.sync.aligned.m8n8.x4.shared.b16 {%0,%1,%2,%3}, [%4];\n"
                 : "=r"(r[0]), "=r"(r[1]), "=r"(r[2]), "=r"(r[3]) : "r"(addr));
}

__device__ __forceinline__ void mma16816(float* c, const uint32_t* a,
                                         const uint32_t* b) {
    asm volatile(
        "mma.sync.aligned.m16n8k16.row.col.f32.bf16.bf16.f32 "
        "{%0,%1,%2,%3}, {%4,%5,%6,%7}, {%8,%9}, {%0,%1,%2,%3};\n"
        : "+f"(c[0]), "+f"(c[1]), "+f"(c[2]), "+f"(c[3])
        : "r"(a[0]), "r"(a[1]), "r"(a[2]), "r"(a[3]), "r"(b[0]), "r"(b[1]));
}

__device__ __forceinline__ uint32_t pack_hilo(float v0, float v1, uint32_t& lo) {
    __nv_bfloat16 h0 = __float2bfloat16(v0);
    __nv_bfloat16 h1 = __float2bfloat16(v1);
    __nv_bfloat16 l0 = __float2bfloat16(v0 - __bfloat162float(h0));
    __nv_bfloat16 l1 = __float2bfloat16(v1 - __bfloat162float(h1));
    __nv_bfloat162 hp; hp.x = h0; hp.y = h1;
    __nv_bfloat162 lp; lp.x = l0; lp.y = l1;
    lo = *(uint32_t*)&lp;
    return *(uint32_t*)&hp;
}

__device__ __forceinline__ int edge_dst(const void* ei, int nEdges, int edge) {
    if (g_idx64) return (int)((const long long*)ei)[(size_t)nEdges + edge];
    return ((const int*)ei)[(size_t)nEdges + edge];
}

#define ROWB 272
#define A_TILE_BYTES (64 * ROWB)     // 17408 (64-row A tile)
#define B_TILE_BYTES (128 * ROWB)    // 34816 (128-row B tile)

// ---------------------------------------------------------------------------
// Kernel 0: detect edge_index dtype
// ---------------------------------------------------------------------------
__global__ void detect_kernel(const unsigned int* __restrict__ ei32) {
    unsigned int acc = 0;
#pragma unroll
    for (int k = 0; k < 8; ++k) acc |= ei32[2 * k + 1];
    g_idx64 = (acc == 0u) ? 1 : 0;
}

// ---------------------------------------------------------------------------
// CSR build kernels
// ---------------------------------------------------------------------------
__global__ void zero_cnt_kernel(int nNodes) {
    int i = blockIdx.x * blockDim.x + threadIdx.x;
    if (i < nNodes) g_cnt[i] = 0;
}

__global__ void hist_kernel(const void* __restrict__ ei, int nEdges, int nNodes) {
    int i = blockIdx.x * blockDim.x + threadIdx.x;
    if (i >= nEdges) return;
    int dst = edge_dst(ei, nEdges, i);
    if ((unsigned)dst < (unsigned)nNodes) atomicAdd(&g_cnt[dst], 1);
}

__global__ void scan1_kernel(int nNodes) {
    __shared__ int wsum[32];
    int i = blockIdx.x * 1024 + threadIdx.x;
    int lane = threadIdx.x & 31, w = threadIdx.x >> 5;
    int v = (i < nNodes) ? g_cnt[i] : 0;
    int inc = v;
#pragma unroll
    for (int off = 1; off < 32; off <<= 1) {
        int t = __shfl_up_sync(0xffffffffu, inc, off);
        if (lane >= off) inc += t;
    }
    if (lane == 31) wsum[w] = inc;
    __syncthreads();
    if (w == 0) {
        int s = (lane < 32) ? wsum[lane] : 0;
#pragma unroll
        for (int off = 1; off < 32; off <<= 1) {
            int t = __shfl_up_sync(0xffffffffu, s, off);
            if (lane >= off) s += t;
        }
        wsum[lane] = s;
    }
    __syncthreads();
    int base = (w > 0) ? wsum[w - 1] : 0;
    int excl = base + inc - v;
    if (i < nNodes) g_off[i] = excl;
    if (threadIdx.x == 1023) g_bsum[blockIdx.x] = base + inc;
}

__global__ void scan2_kernel(int nblocks) {
    if (threadIdx.x == 0) {
        int s = 0;
        for (int b = 0; b < nblocks; ++b) { g_bsumx[b] = s; s += g_bsum[b]; }
    }
}

__global__ void scan3_kernel(int nNodes) {
    int i = blockIdx.x * 1024 + threadIdx.x;
    if (i < nNodes) {
        int o = g_off[i] + g_bsumx[blockIdx.x];
        g_off[i] = o;
        g_cursor[i] = o;
    }
}

__global__ void fill_kernel(const void* __restrict__ ei, int nEdges, int nNodes) {
    int i = blockIdx.x * blockDim.x + threadIdx.x;
    if (i >= nEdges) return;
    int dst = edge_dst(ei, nEdges, i);
    if ((unsigned)dst >= (unsigned)nNodes) return;
    int pos = atomicAdd(&g_cursor[dst], 1);
    g_eid[pos] = i;
}

// ---------------------------------------------------------------------------
// Gather: one warp per node, lane c owns float4 chunk c. Streaming loads.
// ---------------------------------------------------------------------------
__global__ void gather_kernel(const float* __restrict__ e, int nNodes) {
    int gid = blockIdx.x * blockDim.x + threadIdx.x;
    int node = gid >> 5;
    if (node >= nNodes) return;
    int lane = gid & 31;
    int c = lane << 2;
    int start = g_off[node];
    int n = g_cnt[node];
    float4 acc = make_float4(0.f, 0.f, 0.f, 0.f);
    int i = 0;
    for (; i + 4 <= n; i += 4) {
        int e0 = g_eid[start + i];
        int e1 = g_eid[start + i + 1];
        int e2 = g_eid[start + i + 2];
        int e3 = g_eid[start + i + 3];
        float4 v0 = __ldcs((const float4*)&e[(size_t)e0 * DIM + c]);
        float4 v1 = __ldcs((const float4*)&e[(size_t)e1 * DIM + c]);
        float4 v2 = __ldcs((const float4*)&e[(size_t)e2 * DIM + c]);
        float4 v3 = __ldcs((const float4*)&e[(size_t)e3 * DIM + c]);
        acc.x += v0.x + v1.x + v2.x + v3.x;
        acc.y += v0.y + v1.y + v2.y + v3.y;
        acc.z += v0.z + v1.z + v2.z + v3.z;
        acc.w += v0.w + v1.w + v2.w + v3.w;
    }
    for (; i < n; ++i) {
        int e0 = g_eid[start + i];
        float4 v0 = __ldcs((const float4*)&e[(size_t)e0 * DIM + c]);
        acc.x += v0.x; acc.y += v0.y; acc.z += v0.z; acc.w += v0.w;
    }
    *(float4*)&g_msg[(size_t)node * DIM + c] = acc;
}

// ---------------------------------------------------------------------------
// Weight prep. B[n][k] = W[k][n], bf16 hi/lo.
// ---------------------------------------------------------------------------
__global__ void prep_weights(const float* __restrict__ W0,
                             const float* __restrict__ Wh,
                             const float* __restrict__ Wo) {
    int l = blockIdx.x;  // 0..4
    const float* src;
    if (l == 0)      src = W0;
    else if (l == 1) src = W0 + 128 * 128;
    else if (l == 2) src = Wh;
    else if (l == 3) src = Wh + 128 * 128;
    else             src = Wo;
    __nv_bfloat16* dh = g_whi[l];
    __nv_bfloat16* dl = g_wlo[l];
    for (int i = threadIdx.x; i < 128 * 128; i += blockDim.x) {
        int n = i >> 7, k = i & 127;
        float w = src[k * 128 + n];
        __nv_bfloat16 hi = __float2bfloat16(w);
        dh[i] = hi;
        dl[i] = __float2bfloat16(w - __bfloat162float(hi));
    }
}

// ---------------------------------------------------------------------------
// MLP kernel (mma.sync bf16 hi/lo). 64 nodes per block, 256 threads,
// 2 blocks/SM. Warp (wid&1) -> 32-row half; (wid>>1) -> 32-col group.
// Per warp: 2 m-tiles (m16) x 4 n-tiles (n8), acc[2][4][4].
// ---------------------------------------------------------------------------
__device__ __forceinline__ void stage_A(const float* __restrict__ src, int m0,
                                        int nNodes, unsigned char* Ahi,
                                        unsigned char* Alo, int tid) {
#pragma unroll
    for (int i = 0; i < 8; ++i) {
        int id = i * 256 + tid;        // 0..2047 float4s (64 rows x 32 chunks)
        int row = id >> 5;
        int k0 = (id & 31) << 2;
        float4 v = make_float4(0.f, 0.f, 0.f, 0.f);
        int node = m0 + row;
        if (node < nNodes) v = *(const float4*)&src[(size_t)node * DIM + k0];
        uint32_t l01, l23;
        uint32_t h01 = pack_hilo(v.x, v.y, l01);
        uint32_t h23 = pack_hilo(v.z, v.w, l23);
        uint2 uh; uh.x = h01; uh.y = h23;
        uint2 ul; ul.x = l01; ul.y = l23;
        *(uint2*)(Ahi + row * ROWB + k0 * 2) = uh;
        *(uint2*)(Alo + row * ROWB + k0 * 2) = ul;
    }
}

__device__ __forceinline__ void stage_B(int l, unsigned char* Bhi,
                                        unsigned char* Blo, int tid) {
    const float4* sh = (const float4*)g_whi[l];
    const float4* sl = (const float4*)g_wlo[l];
#pragma unroll
    for (int i = 0; i < 8; ++i) {
        int id = i * 256 + tid;        // 0..2047 float4s (16 per row)
        int row = id >> 4;
        int c16 = id & 15;
        *(float4*)(Bhi + row * ROWB + c16 * 16) = sh[id];
        *(float4*)(Blo + row * ROWB + c16 * 16) = sl[id];
    }
}

__device__ __forceinline__ void clear_acc(float acc[2][4][4]) {
#pragma unroll
    for (int m = 0; m < 2; ++m)
#pragma unroll
        for (int n = 0; n < 4; ++n)
#pragma unroll
            for (int c = 0; c < 4; ++c) acc[m][n][c] = 0.f;
}

__device__ __forceinline__ void gemm_unit(float acc[2][4][4],
                                          uint32_t AHI, uint32_t ALO,
                                          uint32_t BHI, uint32_t BLO,
                                          uint32_t aoff, uint32_t boff) {
#pragma unroll
    for (int k0 = 0; k0 < 128; k0 += 16) {
        uint32_t ah[2][4], al[2][4];
        ldsm4(ah[0], AHI + aoff + k0 * 2);
        ldsm4(ah[1], AHI + aoff + 16 * ROWB + k0 * 2);
        ldsm4(al[0], ALO + aoff + k0 * 2);
        ldsm4(al[1], ALO + aoff + 16 * ROWB + k0 * 2);
#pragma unroll
        for (int g = 0; g < 2; ++g) {
            uint32_t bh[4], bl[4];
            ldsm4(bh, BHI + boff + g * 16 * ROWB + k0 * 2);
            ldsm4(bl, BLO + boff + g * 16 * ROWB + k0 * 2);
#pragma unroll
            for (int t = 0; t < 2; ++t) {
                int nt = g * 2 + t;
#pragma unroll
                for (int mt = 0; mt < 2; ++mt) {
                    mma16816(acc[mt][nt], ah[mt], bh + t * 2);
                    mma16816(acc[mt][nt], ah[mt], bl + t * 2);
                    mma16816(acc[mt][nt], al[mt], bh + t * 2);
                }
            }
        }
    }
}

__device__ __forceinline__ void epi_relu(float acc[2][4][4],
                                         const float* __restrict__ sbias,
                                         unsigned char* Ahi, unsigned char* Alo,
                                         int warp_m, int warp_n, int lane) {
    int rbase = warp_m * 32 + (lane >> 2);
    int cbase = warp_n * 32 + 2 * (lane & 3);
#pragma unroll
    for (int mt = 0; mt < 2; ++mt) {
#pragma unroll
        for (int nt = 0; nt < 4; ++nt) {
            int c = cbase + nt * 8;
            float bb0 = sbias[c], bb1 = sbias[c + 1];
            int r0 = rbase + mt * 16;
            float v0 = fmaxf(acc[mt][nt][0] + bb0, 0.f);
            float v1 = fmaxf(acc[mt][nt][1] + bb1, 0.f);
            float v2 = fmaxf(acc[mt][nt][2] + bb0, 0.f);
            float v3 = fmaxf(acc[mt][nt][3] + bb1, 0.f);
            uint32_t lo;
            uint32_t hi = pack_hilo(v0, v1, lo);
            *(uint32_t*)(Ahi + r0 * ROWB + c * 2) = hi;
            *(uint32_t*)(Alo + r0 * ROWB + c * 2) = lo;
            hi = pack_hilo(v2, v3, lo);
            *(uint32_t*)(Ahi + (r0 + 8) * ROWB + c * 2) = hi;
            *(uint32_t*)(Alo + (r0 + 8) * ROWB + c * 2) = lo;
        }
    }
}

// smem: header 5120 + A hi/lo (64-row) + B hi/lo (128-row)
#define SMEM_AOFF 5120
#define SMEM_TOTAL_MLP (SMEM_AOFF + 2 * A_TILE_BYTES + 2 * B_TILE_BYTES) // 109568

__global__ __launch_bounds__(256, 2)
void mlp_mma_kernel(const float* __restrict__ x,
                    const float* __restrict__ b0v,
                    const float* __restrict__ bhv,
                    const float* __restrict__ bov,
                    const float* __restrict__ gnw, const float* __restrict__ gnb,
                    float* __restrict__ out, int nNodes) {
    extern __shared__ unsigned char smem[];
    float* sb   = (float*)smem;            // [4][128] biases
    float* sgw  = (float*)(smem + 2048);
    float* sgb  = (float*)(smem + 2560);
    float* ps   = (float*)(smem + 3072);   // [4][64]
    float* pq   = (float*)(smem + 4096);   // [4][64]
    unsigned char* Ahi = smem + SMEM_AOFF;
    unsigned char* Alo = Ahi + A_TILE_BYTES;
    unsigned char* Bhi = Alo + A_TILE_BYTES;
    unsigned char* Blo = Bhi + B_TILE_BYTES;

    const uint32_t sb32 = smem_to_u32(smem);
    const uint32_t AHI = sb32 + SMEM_AOFF;
    const uint32_t ALO = AHI + A_TILE_BYTES;
    const uint32_t BHI = ALO + A_TILE_BYTES;
    const uint32_t BLO = BHI + B_TILE_BYTES;

    const int tid = threadIdx.x;
    const int wid = tid >> 5, lane = tid & 31;
    const int warp_m = wid & 1, warp_n = wid >> 1;
    const int m0 = blockIdx.x * 64;

    const uint32_t aoff =
        (uint32_t)(warp_m * 32 + (lane & 15)) * ROWB + (((lane >> 4) & 1) * 8) * 2;
    const uint32_t boff =
        (uint32_t)(warp_n * 32 + ((lane >> 4) & 1) * 8 + (lane & 7)) * ROWB +
        (((lane >> 3) & 1) * 8) * 2;

    if (tid < 128) {
        sb[tid]       = b0v[tid];
        sb[128 + tid] = bhv[tid];
        sb[256 + tid] = bhv[128 + tid];
        sb[384 + tid] = bov[tid];
        sgw[tid] = gnw[tid];
        sgb[tid] = gnb[tid];
    }

    float acc[2][4][4];
    clear_acc(acc);

    // ---- layer 0, part 1: A = x, B = W0[k<128] ----
    stage_A(x, m0, nNodes, Ahi, Alo, tid);
    stage_B(0, Bhi, Blo, tid);
    __syncthreads();
    gemm_unit(acc, AHI, ALO, BHI, BLO, aoff, boff);
    __syncthreads();

    // ---- layer 0, part 2: A = msg, B = W0[k>=128] (accumulate) ----
    stage_A((const float*)g_msg, m0, nNodes, Ahi, Alo, tid);
    stage_B(1, Bhi, Blo, tid);
    __syncthreads();
    gemm_unit(acc, AHI, ALO, BHI, BLO, aoff, boff);
    __syncthreads();

    // ---- hidden layers ----
#pragma unroll
    for (int l = 0; l < 2; ++l) {
        epi_relu(acc, sb + l * 128, Ahi, Alo, warp_m, warp_n, lane);
        stage_B(2 + l, Bhi, Blo, tid);
        __syncthreads();
        clear_acc(acc);
        gemm_unit(acc, AHI, ALO, BHI, BLO, aoff, boff);
        __syncthreads();
    }

    // ---- output layer ----
    epi_relu(acc, sb + 256, Ahi, Alo, warp_m, warp_n, lane);
    stage_B(4, Bhi, Blo, tid);
    __syncthreads();
    clear_acc(acc);
    gemm_unit(acc, AHI, ALO, BHI, BLO, aoff, boff);

    // ---- GroupNorm + affine + residual ----
    const int rq = lane >> 2;
    const int cbase = warp_n * 32 + 2 * (lane & 3);
#pragma unroll
    for (int mt = 0; mt < 2; ++mt)
#pragma unroll
        for (int nt = 0; nt < 4; ++nt) {
            int c = cbase + nt * 8;
            acc[mt][nt][0] += sb[384 + c];
            acc[mt][nt][1] += sb[384 + c + 1];
            acc[mt][nt][2] += sb[384 + c];
            acc[mt][nt][3] += sb[384 + c + 1];
        }
    float s[4] = {0.f, 0.f, 0.f, 0.f}, q[4] = {0.f, 0.f, 0.f, 0.f};
#pragma unroll
    for (int mt = 0; mt < 2; ++mt)
#pragma unroll
        for (int nt = 0; nt < 4; ++nt) {
            float a0 = acc[mt][nt][0], a1 = acc[mt][nt][1];
            float a2 = acc[mt][nt][2], a3 = acc[mt][nt][3];
            s[mt * 2]     += a0 + a1;
            q[mt * 2]     += a0 * a0 + a1 * a1;
            s[mt * 2 + 1] += a2 + a3;
            q[mt * 2 + 1] += a2 * a2 + a3 * a3;
        }
#pragma unroll
    for (int off = 1; off <= 2; off <<= 1) {
#pragma unroll
        for (int i = 0; i < 4; ++i) {
            s[i] += __shfl_xor_sync(0xffffffffu, s[i], off);
            q[i] += __shfl_xor_sync(0xffffffffu, q[i], off);
        }
    }
    if ((lane & 3) == 0) {
        int r0 = warp_m * 32 + rq;
        ps[warp_n * 64 + r0]      = s[0];
        ps[warp_n * 64 + r0 + 8]  = s[1];
        ps[warp_n * 64 + r0 + 16] = s[2];
        ps[warp_n * 64 + r0 + 24] = s[3];
        pq[warp_n * 64 + r0]      = q[0];
        pq[warp_n * 64 + r0 + 8]  = q[1];
        pq[warp_n * 64 + r0 + 16] = q[2];
        pq[warp_n * 64 + r0 + 24] = q[3];
    }
    __syncthreads();
#pragma unroll
    for (int mt = 0; mt < 2; ++mt) {
#pragma unroll
        for (int h = 0; h < 2; ++h) {
            int r = warp_m * 32 + mt * 16 + h * 8 + rq;
            float ts = ps[r] + ps[64 + r] + ps[128 + r] + ps[192 + r];
            float tq = pq[r] + pq[64 + r] + pq[128 + r] + pq[192 + r];
            float mean = ts * (1.f / 128.f);
            float var = tq * (1.f / 128.f) - mean * mean;
            float rstd = rsqrtf(var + 1e-5f);
            int node = m0 + r;
            if (node < nNodes) {
#pragma unroll
                for (int nt = 0; nt < 4; ++nt) {
                    int c = cbase + nt * 8;
                    float v0 = acc[mt][nt][h * 2 + 0];
                    float v1 = acc[mt][nt][h * 2 + 1];
                    float2 xv = *(const float2*)&x[(size_t)node * DIM + c];
                    float2 o;
                    o.x = (v0 - mean) * rstd * sgw[c]     + sgb[c]     + xv.x;
                    o.y = (v1 - mean) * rstd * sgw[c + 1] + sgb[c + 1] + xv.y;
                    *(float2*)&out[(size_t)node * DIM + c] = o;
                }
            }
        }
    }
}

// ---------------------------------------------------------------------------
extern "C" void kernel_launch(void* const* d_in, const int* in_sizes, int n_in,
                              void* d_out, int out_size) {
    const float* x  = (const float*)d_in[0];
    const float* e  = (const float*)d_in[1];
    const void*  ei = d_in[2];
    const float* W0 = (const float*)d_in[3];
    const float* b0 = (const float*)d_in[4];
    const float* Wh = (const float*)d_in[5];
    const float* bh = (const float*)d_in[6];
    const float* Wo = (const float*)d_in[7];
    const float* bo = (const float*)d_in[8];
    const float* gnw = (const float*)d_in[9];
    const float* gnb = (const float*)d_in[10];
    float* out = (float*)d_out;

    int nNodes = in_sizes[0] / DIM;
    int nEdges = in_sizes[1] / DIM;
    if (nNodes > MAX_NODES) nNodes = MAX_NODES;
    if (nEdges > MAX_EDGES) nEdges = MAX_EDGES;

    cudaFuncSetAttribute(mlp_mma_kernel, cudaFuncAttributeMaxDynamicSharedMemorySize,
                         SMEM_TOTAL_MLP);

    const int scanBlocks = (nNodes + 1023) / 1024;

    // 0) detect edge_index dtype
    detect_kernel<<<1, 1>>>((const unsigned int*)ei);

    // 1) weight prep (independent)
    prep_weights<<<5, 256>>>(W0, Wh, Wo);

    // 2) CSR build
    zero_cnt_kernel<<<(nNodes + 255) / 256, 256>>>(nNodes);
    hist_kernel<<<(nEdges + 255) / 256, 256>>>(ei, nEdges, nNodes);
    scan1_kernel<<<scanBlocks, 1024>>>(nNodes);
    scan2_kernel<<<1, 32>>>(scanBlocks);
    scan3_kernel<<<scanBlocks, 1024>>>(nNodes);
    fill_kernel<<<(nEdges + 255) / 256, 256>>>(ei, nEdges, nNodes);

    // 3) gather
    long long gthreads = (long long)nNodes * 32;
    gather_kernel<<<(int)((gthreads + 255) / 256), 256>>>(e, nNodes);

    // 4) fused tensor-core MLP + GroupNorm + residual (64 nodes/block, occ 2)
    int mblocks = (nNodes + 63) / 64;
    mlp_mma_kernel<<<mblocks, 256, SMEM_TOTAL_MLP>>>(x, b0, bh, bo, gnw, gnb,
                                                     out, nNodes);
}